// round 15
// baseline (speedup 1.0000x reference)
#include <cuda_runtime.h>

#define NSTEP  25
#define NIN    9
#define NHID   100
#define CAP    80           // max list entries/thread (P(exceed) ~ 0)
#define HPAD   100          // pad index -> sW2[100] = (0,0)
// never spikes within 25 steps iff c <= 0.05/(1-0.95^25) = 0.069194
// CSKIP*14.4522 = 0.99720 < 1: 2.8e-3 margin >> fp32 drift.
#define CSKIP   0.0690f
// spikes at EVERY step if c > 1.05 (fixpoint 20(c-1) > 1); 1.06 -> margin 0.2
#define CALWAYS 1.06f

__global__ __launch_bounds__(64) void snn_kernel(
    const float* __restrict__ x,
    const float* __restrict__ W1,
    const float* __restrict__ b1,
    const float* __restrict__ W2,
    const float* __restrict__ b2,
    float* __restrict__ out,
    int batch)
{
    // W1 padded to 12 floats/row: [w0..w8, b1, 0, 0] (phase 1 only)
    __shared__ float4 sW1[NHID * 3];
    __shared__ float2 sW2[NHID + 1];      // (W2[0][h], W2[1][h]); row 100 = 0
    __shared__ float  sb2[2];
    __shared__ float  sC[CAP * 64];       // active currents, column layout
    __shared__ unsigned char sH[CAP * 64];// active neuron indices

    {
        float* sW1f = (float*)sW1;
        for (int h = threadIdx.x; h < NHID + 1; h += blockDim.x) {
            if (h < NHID) {
#pragma unroll
                for (int i = 0; i < NIN; i++) sW1f[h * 12 + i] = W1[h * NIN + i];
                sW1f[h * 12 + 9]  = b1[h];
                sW1f[h * 12 + 10] = 0.0f;
                sW1f[h * 12 + 11] = 0.0f;
            }
            sW2[h] = (h < NHID) ? make_float2(W2[h], W2[NHID + h])
                                : make_float2(0.0f, 0.0f);
        }
        if (threadIdx.x < 2) sb2[threadIdx.x] = b2[threadIdx.x];
    }
    __syncthreads();

    const int tid = threadIdx.x;
    int b = blockIdx.x * blockDim.x + tid;
    if (b >= batch) return;

    float xv[NIN];
#pragma unroll
    for (int i = 0; i < NIN; i++) xv[i] = __ldg(&x[(size_t)b * NIN + i]);

    // ---- Phase 1: cur1 for all 100 neurons; classify ----
    //  c <= CSKIP        -> dead, drop
    //  c >  CALWAYS      -> spikes every step, fold weights into (ws0, ws1)
    //  else              -> compacted list
    int n = 0;
    float ws0 = 0.0f, ws1 = 0.0f;
    for (int h = 0; h < NHID; h += 4) {
#pragma unroll
        for (int j = 0; j < 4; j++) {
            float4 a0 = sW1[(h + j) * 3 + 0];
            float4 a1 = sW1[(h + j) * 3 + 1];
            float4 a2 = sW1[(h + j) * 3 + 2];
            float ca = a2.y;
            ca = fmaf(xv[0], a0.x, ca); ca = fmaf(xv[1], a0.y, ca);
            ca = fmaf(xv[2], a0.z, ca); ca = fmaf(xv[3], a0.w, ca);
            float cb = xv[4] * a1.x;
            cb = fmaf(xv[5], a1.y, cb); cb = fmaf(xv[6], a1.z, cb);
            cb = fmaf(xv[7], a1.w, cb); cb = fmaf(xv[8], a2.x, cb);
            float cc = ca + cb;
            if (cc > CSKIP) {
                if (cc > CALWAYS) {
                    float2 w = sW2[h + j];
                    ws0 += w.x;
                    ws1 += w.y;
                } else if (n < CAP) {
                    sC[n * 64 + tid] = cc;
                    sH[n * 64 + tid] = (unsigned char)(h + j);
                    n++;
                }
            }
        }
    }

    // warp-uniform trip count (groups of 8); pad own tail with inert entries
    int Lw = (int)__reduce_max_sync(0xffffffffu, (unsigned)n);
    int Le = (Lw + 7) & ~7;
    for (int e = n; e < Le; e++) {
        sC[e * 64 + tid] = 0.0f;          // never spikes
        sH[e * 64 + tid] = HPAD;          // -> zero weights
    }

    // acc starts at the always-spiker contribution (present at every t)
    float acc0[NSTEP], acc1[NSTEP];
#pragma unroll
    for (int t = 0; t < NSTEP; t++) { acc0[t] = ws0; acc1[t] = ws1; }

    // ---- Phase 2: exact R3 recurrence, 8 independent chains per group ----
    for (int e = 0; e < Le; e += 8) {
        float c[8];
        float2 w[8];
#pragma unroll
        for (int j = 0; j < 8; j++) {
            c[j] = sC[(e + j) * 64 + tid];
            w[j] = sW2[sH[(e + j) * 64 + tid]];
        }
        float m[8], r[8];
#pragma unroll
        for (int j = 0; j < 8; j++) { m[j] = 0.0f; r[j] = 0.0f; }

#pragma unroll
        for (int t = 0; t < NSTEP; t++) {
#pragma unroll
            for (int j = 0; j < 8; j++)
                m[j] = fmaf(0.95f, m[j], c[j]) - r[j];
#pragma unroll
            for (int j = 0; j < 8; j++)
                asm("set.gt.f32.f32 %0, %1, 0f3F800000;" : "=f"(r[j]) : "f"(m[j]));
#pragma unroll
            for (int j = 0; j < 8; j++) {
                acc0[t] = fmaf(r[j], w[j].x, acc0[t]);
                acc1[t] = fmaf(r[j], w[j].y, acc1[t]);
            }
        }
    }

    // ---- Layer-2 LIF recurrence + record mem2 each step ----
    const float bb0 = sb2[0], bb1 = sb2[1];
    float m20 = 0.0f, m21 = 0.0f;
    float2* outv = (float2*)out;
#pragma unroll
    for (int t = 0; t < NSTEP; t++) {
        float rr0, rr1;                        // reset from PREVIOUS mem2
        asm("set.gt.f32.f32 %0, %1, 0f3F800000;" : "=f"(rr0) : "f"(m20));
        asm("set.gt.f32.f32 %0, %1, 0f3F800000;" : "=f"(rr1) : "f"(m21));
        m20 = fmaf(0.95f, m20, acc0[t] + bb0) - rr0;
        m21 = fmaf(0.95f, m21, acc1[t] + bb1) - rr1;
        outv[(size_t)t * batch + b] = make_float2(m20, m21);
    }
}

extern "C" void kernel_launch(void* const* d_in, const int* in_sizes, int n_in,
                              void* d_out, int out_size)
{
    const float* x  = (const float*)d_in[0];
    const float* W1 = (const float*)d_in[1];
    const float* b1 = (const float*)d_in[2];
    const float* W2 = (const float*)d_in[3];
    const float* b2 = (const float*)d_in[4];
    float* out = (float*)d_out;

    int batch = in_sizes[0] / NIN;
    const int threads = 64;
    int blocks = (batch + threads - 1) / threads;
    snn_kernel<<<blocks, threads>>>(x, W1, b1, W2, b2, out, batch);
}

// round 16
// speedup vs baseline: 1.0057x; 1.0057x over previous
#include <cuda_runtime.h>

#define NSTEP  25
#define NIN    9
#define NHID   100
#define CAP    80           // max list entries/thread (P(exceed) ~ 0)
#define HPAD   100          // pad index -> sW2[100] = (0,0)
// never spikes within 25 steps iff c <= 0.05/(1-0.95^25) = 0.069194
// CSKIP*14.4522 = 0.99720 < 1: 2.8e-3 margin >> fp32 drift.
#define CSKIP   0.0690f
// spikes at EVERY step if c > 1.05 (m_t >= min(c, 20(c-1)) > 1); 1.06 -> margin
#define CALWAYS 1.06f

__global__ __launch_bounds__(64) void snn_kernel(
    const float* __restrict__ x,
    const float* __restrict__ W1,
    const float* __restrict__ b1,
    const float* __restrict__ W2,
    const float* __restrict__ b2,
    float* __restrict__ out,
    int batch)
{
    // W1 padded to 12 floats/row: [w0..w8, b1, 0, 0] (phase 1 only)
    __shared__ float4 sW1[NHID * 3];
    __shared__ float2 sW2[NHID + 1];      // (W2[0][h], W2[1][h]); row 100 = 0
    __shared__ float  sb2[2];
    __shared__ float  sC[CAP * 64];       // active currents, column layout
    __shared__ unsigned char sH[CAP * 64];// active neuron indices

    {
        float* sW1f = (float*)sW1;
        for (int h = threadIdx.x; h < NHID + 1; h += blockDim.x) {
            if (h < NHID) {
#pragma unroll
                for (int i = 0; i < NIN; i++) sW1f[h * 12 + i] = W1[h * NIN + i];
                sW1f[h * 12 + 9]  = b1[h];
                sW1f[h * 12 + 10] = 0.0f;
                sW1f[h * 12 + 11] = 0.0f;
            }
            sW2[h] = (h < NHID) ? make_float2(W2[h], W2[NHID + h])
                                : make_float2(0.0f, 0.0f);
        }
        if (threadIdx.x < 2) sb2[threadIdx.x] = b2[threadIdx.x];
    }
    __syncthreads();

    const int tid = threadIdx.x;
    int b = blockIdx.x * blockDim.x + tid;
    if (b >= batch) return;

    float xv[NIN];
#pragma unroll
    for (int i = 0; i < NIN; i++) xv[i] = __ldg(&x[(size_t)b * NIN + i]);

    // ---- Phase 1: cur1 for all 100 neurons; classify ----
    //  c <= CSKIP   -> never spikes, drop
    //  c >  CALWAYS -> spikes every step, fold weights into (ws0, ws1)
    //  else         -> compacted list
    int n = 0;
    float ws0 = 0.0f, ws1 = 0.0f;
    for (int h = 0; h < NHID; h += 2) {
#pragma unroll
        for (int j = 0; j < 2; j++) {
            float4 a0 = sW1[(h + j) * 3 + 0];
            float4 a1 = sW1[(h + j) * 3 + 1];
            float4 a2 = sW1[(h + j) * 3 + 2];
            float ca = a2.y;
            ca = fmaf(xv[0], a0.x, ca); ca = fmaf(xv[1], a0.y, ca);
            ca = fmaf(xv[2], a0.z, ca); ca = fmaf(xv[3], a0.w, ca);
            float cb = xv[4] * a1.x;
            cb = fmaf(xv[5], a1.y, cb); cb = fmaf(xv[6], a1.z, cb);
            cb = fmaf(xv[7], a1.w, cb); cb = fmaf(xv[8], a2.x, cb);
            float cc = ca + cb;
            if (cc > CSKIP) {
                if (cc > CALWAYS) {
                    float2 w = sW2[h + j];
                    ws0 += w.x;
                    ws1 += w.y;
                } else if (n < CAP) {
                    sC[n * 64 + tid] = cc;
                    sH[n * 64 + tid] = (unsigned char)(h + j);
                    n++;
                }
            }
        }
    }

    // warp-uniform trip count; pad own tail with inert entries
    int Lw = (int)__reduce_max_sync(0xffffffffu, (unsigned)n);
    int Le = (Lw + 3) & ~3;
    for (int e = n; e < Le; e++) {
        sC[e * 64 + tid] = 0.0f;          // never spikes
        sH[e * 64 + tid] = HPAD;          // -> zero weights
    }

    // acc starts at the always-spiker contribution (present at every t)
    float acc0[NSTEP], acc1[NSTEP];
#pragma unroll
    for (int t = 0; t < NSTEP; t++) { acc0[t] = ws0; acc1[t] = ws1; }

    // ---- Phase 2: exact R3/R14 recurrence over compacted list, 4 chains ----
    for (int e = 0; e < Le; e += 4) {
        float c0 = sC[(e + 0) * 64 + tid];
        float c1 = sC[(e + 1) * 64 + tid];
        float c2 = sC[(e + 2) * 64 + tid];
        float c3 = sC[(e + 3) * 64 + tid];
        float2 w0 = sW2[sH[(e + 0) * 64 + tid]];
        float2 w1 = sW2[sH[(e + 1) * 64 + tid]];
        float2 w2 = sW2[sH[(e + 2) * 64 + tid]];
        float2 w3 = sW2[sH[(e + 3) * 64 + tid]];

        float m0 = 0.f, m1 = 0.f, m2 = 0.f, m3 = 0.f;   // membranes
        float r0 = 0.f, r1 = 0.f, r2 = 0.f, r3 = 0.f;   // spikes (float 0/1)

#pragma unroll
        for (int t = 0; t < NSTEP; t++) {
            m0 = fmaf(0.95f, m0, c0) - r0;
            m1 = fmaf(0.95f, m1, c1) - r1;
            m2 = fmaf(0.95f, m2, c2) - r2;
            m3 = fmaf(0.95f, m3, c3) - r3;
            asm("set.gt.f32.f32 %0, %1, 0f3F800000;" : "=f"(r0) : "f"(m0));
            asm("set.gt.f32.f32 %0, %1, 0f3F800000;" : "=f"(r1) : "f"(m1));
            asm("set.gt.f32.f32 %0, %1, 0f3F800000;" : "=f"(r2) : "f"(m2));
            asm("set.gt.f32.f32 %0, %1, 0f3F800000;" : "=f"(r3) : "f"(m3));
            acc0[t] = fmaf(r0, w0.x, acc0[t]);  acc1[t] = fmaf(r0, w0.y, acc1[t]);
            acc0[t] = fmaf(r1, w1.x, acc0[t]);  acc1[t] = fmaf(r1, w1.y, acc1[t]);
            acc0[t] = fmaf(r2, w2.x, acc0[t]);  acc1[t] = fmaf(r2, w2.y, acc1[t]);
            acc0[t] = fmaf(r3, w3.x, acc0[t]);  acc1[t] = fmaf(r3, w3.y, acc1[t]);
        }
    }

    // ---- Layer-2 LIF recurrence + record mem2 each step ----
    const float bb0 = sb2[0], bb1 = sb2[1];
    float m20 = 0.0f, m21 = 0.0f;
    float2* outv = (float2*)out;
#pragma unroll
    for (int t = 0; t < NSTEP; t++) {
        float rr0, rr1;                        // reset from PREVIOUS mem2
        asm("set.gt.f32.f32 %0, %1, 0f3F800000;" : "=f"(rr0) : "f"(m20));
        asm("set.gt.f32.f32 %0, %1, 0f3F800000;" : "=f"(rr1) : "f"(m21));
        m20 = fmaf(0.95f, m20, acc0[t] + bb0) - rr0;
        m21 = fmaf(0.95f, m21, acc1[t] + bb1) - rr1;
        outv[(size_t)t * batch + b] = make_float2(m20, m21);
    }
}

extern "C" void kernel_launch(void* const* d_in, const int* in_sizes, int n_in,
                              void* d_out, int out_size)
{
    const float* x  = (const float*)d_in[0];
    const float* W1 = (const float*)d_in[1];
    const float* b1 = (const float*)d_in[2];
    const float* W2 = (const float*)d_in[3];
    const float* b2 = (const float*)d_in[4];
    float* out = (float*)d_out;

    int batch = in_sizes[0] / NIN;
    const int threads = 64;
    int blocks = (batch + threads - 1) / threads;
    snn_kernel<<<blocks, threads>>>(x, W1, b1, W2, b2, out, batch);
}

// round 17
// speedup vs baseline: 1.1223x; 1.1159x over previous
#include <cuda_runtime.h>

#define NSTEP  25
#define NIN    9
#define NHID   100
#define CAP    80           // max list entries/thread (P(exceed) ~ 0)
#define HPAD   100          // pad index -> sW2[100] = (0,0)
// never spikes within 25 steps iff c <= 0.05/(1-0.95^25) = 0.069194
// CSKIP*14.4522 = 0.99720 < 1: 2.8e-3 margin >> fp32 drift.
#define CSKIP  0.0690f

__global__ __launch_bounds__(64) void snn_kernel(
    const float* __restrict__ x,
    const float* __restrict__ W1,
    const float* __restrict__ b1,
    const float* __restrict__ W2,
    const float* __restrict__ b2,
    float* __restrict__ out,
    int batch)
{
    // W1 padded to 12 floats/row: [w0..w8, b1, 0, 0] (phase 1 only)
    __shared__ float4 sW1[NHID * 3];
    __shared__ float2 sW2[NHID + 1];      // (W2[0][h], W2[1][h]); row 100 = 0
    __shared__ float  sb2[2];
    __shared__ float  sC[CAP * 64];       // active currents, column layout
    __shared__ unsigned char sH[CAP * 64];// active neuron indices

    {
        float* sW1f = (float*)sW1;
        for (int h = threadIdx.x; h < NHID + 1; h += blockDim.x) {
            if (h < NHID) {
#pragma unroll
                for (int i = 0; i < NIN; i++) sW1f[h * 12 + i] = W1[h * NIN + i];
                sW1f[h * 12 + 9]  = b1[h];
                sW1f[h * 12 + 10] = 0.0f;
                sW1f[h * 12 + 11] = 0.0f;
            }
            sW2[h] = (h < NHID) ? make_float2(W2[h], W2[NHID + h])
                                : make_float2(0.0f, 0.0f);
        }
        if (threadIdx.x < 2) sb2[threadIdx.x] = b2[threadIdx.x];
    }
    __syncthreads();

    const int tid = threadIdx.x;
    int b = blockIdx.x * blockDim.x + tid;
    if (b >= batch) return;

    float xv[NIN];
#pragma unroll
    for (int i = 0; i < NIN; i++) xv[i] = __ldg(&x[(size_t)b * NIN + i]);

    // ---- Phase 1: compute cur1 for all 100 neurons, compact actives ----
    int n = 0;
    for (int h = 0; h < NHID; h += 2) {
#pragma unroll
        for (int j = 0; j < 2; j++) {
            float4 a0 = sW1[(h + j) * 3 + 0];
            float4 a1 = sW1[(h + j) * 3 + 1];
            float4 a2 = sW1[(h + j) * 3 + 2];
            float ca = a2.y;
            ca = fmaf(xv[0], a0.x, ca); ca = fmaf(xv[1], a0.y, ca);
            ca = fmaf(xv[2], a0.z, ca); ca = fmaf(xv[3], a0.w, ca);
            float cb = xv[4] * a1.x;
            cb = fmaf(xv[5], a1.y, cb); cb = fmaf(xv[6], a1.z, cb);
            cb = fmaf(xv[7], a1.w, cb); cb = fmaf(xv[8], a2.x, cb);
            float cc = ca + cb;
            if (cc > CSKIP && n < CAP - 4) {  // can spike within 25 steps
                sC[n * 64 + tid] = cc;
                sH[n * 64 + tid] = (unsigned char)(h + j);
                n++;
            }
        }
    }

    // warp-uniform trip count; pad own tail (incl. one prefetch group) inert
    int Lw = (int)__reduce_max_sync(0xffffffffu, (unsigned)n);
    int Le = (Lw + 3) & ~3;
    for (int e = n; e < Le + 4; e++) {
        sC[e * 64 + tid] = 0.0f;          // never spikes
        sH[e * 64 + tid] = HPAD;          // -> zero weights
    }

    float acc0[NSTEP], acc1[NSTEP];
#pragma unroll
    for (int t = 0; t < NSTEP; t++) { acc0[t] = 0.0f; acc1[t] = 0.0f; }

    // ---- Phase 2: R14 recurrence, 4 chains, prefetched group heads ----
    float c0 = sC[0 * 64 + tid], c1 = sC[1 * 64 + tid];
    float c2 = sC[2 * 64 + tid], c3 = sC[3 * 64 + tid];
    float2 w0 = sW2[sH[0 * 64 + tid]];
    float2 w1 = sW2[sH[1 * 64 + tid]];
    float2 w2 = sW2[sH[2 * 64 + tid]];
    float2 w3 = sW2[sH[3 * 64 + tid]];

    for (int e = 0; e < Le; e += 4) {
        // prefetch next group (always valid: tail padded to Le+4)
        const int ep = e + 4;
        float nc0 = sC[(ep + 0) * 64 + tid];
        float nc1 = sC[(ep + 1) * 64 + tid];
        float nc2 = sC[(ep + 2) * 64 + tid];
        float nc3 = sC[(ep + 3) * 64 + tid];
        float2 nw0 = sW2[sH[(ep + 0) * 64 + tid]];
        float2 nw1 = sW2[sH[(ep + 1) * 64 + tid]];
        float2 nw2 = sW2[sH[(ep + 2) * 64 + tid]];
        float2 nw3 = sW2[sH[(ep + 3) * 64 + tid]];

        float m0 = 0.f, m1 = 0.f, m2 = 0.f, m3 = 0.f;   // membranes
        float r0 = 0.f, r1 = 0.f, r2 = 0.f, r3 = 0.f;   // spikes (float 0/1)

#pragma unroll
        for (int t = 0; t < NSTEP; t++) {
            m0 = fmaf(0.95f, m0, c0) - r0;
            m1 = fmaf(0.95f, m1, c1) - r1;
            m2 = fmaf(0.95f, m2, c2) - r2;
            m3 = fmaf(0.95f, m3, c3) - r3;
            asm("set.gt.f32.f32 %0, %1, 0f3F800000;" : "=f"(r0) : "f"(m0));
            asm("set.gt.f32.f32 %0, %1, 0f3F800000;" : "=f"(r1) : "f"(m1));
            asm("set.gt.f32.f32 %0, %1, 0f3F800000;" : "=f"(r2) : "f"(m2));
            asm("set.gt.f32.f32 %0, %1, 0f3F800000;" : "=f"(r3) : "f"(m3));
            acc0[t] = fmaf(r0, w0.x, acc0[t]);  acc1[t] = fmaf(r0, w0.y, acc1[t]);
            acc0[t] = fmaf(r1, w1.x, acc0[t]);  acc1[t] = fmaf(r1, w1.y, acc1[t]);
            acc0[t] = fmaf(r2, w2.x, acc0[t]);  acc1[t] = fmaf(r2, w2.y, acc1[t]);
            acc0[t] = fmaf(r3, w3.x, acc0[t]);  acc1[t] = fmaf(r3, w3.y, acc1[t]);
        }

        // rotate prefetched registers in
        c0 = nc0; c1 = nc1; c2 = nc2; c3 = nc3;
        w0 = nw0; w1 = nw1; w2 = nw2; w3 = nw3;
    }

    // ---- Layer-2 LIF recurrence + record mem2 each step ----
    const float bb0 = sb2[0], bb1 = sb2[1];
    float m20 = 0.0f, m21 = 0.0f;
    float2* outv = (float2*)out;
#pragma unroll
    for (int t = 0; t < NSTEP; t++) {
        float rr0, rr1;                        // reset from PREVIOUS mem2
        asm("set.gt.f32.f32 %0, %1, 0f3F800000;" : "=f"(rr0) : "f"(m20));
        asm("set.gt.f32.f32 %0, %1, 0f3F800000;" : "=f"(rr1) : "f"(m21));
        m20 = fmaf(0.95f, m20, acc0[t] + bb0) - rr0;
        m21 = fmaf(0.95f, m21, acc1[t] + bb1) - rr1;
        outv[(size_t)t * batch + b] = make_float2(m20, m21);
    }
}

extern "C" void kernel_launch(void* const* d_in, const int* in_sizes, int n_in,
                              void* d_out, int out_size)
{
    const float* x  = (const float*)d_in[0];
    const float* W1 = (const float*)d_in[1];
    const float* b1 = (const float*)d_in[2];
    const float* W2 = (const float*)d_in[3];
    const float* b2 = (const float*)d_in[4];
    float* out = (float*)d_out;

    int batch = in_sizes[0] / NIN;
    const int threads = 64;
    int blocks = (batch + threads - 1) / threads;
    snn_kernel<<<blocks, threads>>>(x, W1, b1, W2, b2, out, batch);
}